// round 14
// baseline (speedup 1.0000x reference)
#include <cuda_runtime.h>
#include <math.h>

#define BATCH      256
#define T_LEN      65536
#define L_CHUNK    32
#define W_WARM     32                      // window = exactly previous chunk
#define CPB        128                     // chunks (= threads) per block
#define REGION     (CPB * L_CHUNK)         // 4096 floats = 16KB
#define RB_PER_ROW (T_LEN / REGION)        // 16 regions per batch row
#define NREG       (BATCH * RB_PER_ROW)    // 4096 regions
#define NR         4                       // regions per block (pipelined)
#define GRID       (NREG / NR)             // 1024 blocks
#define BUFWORDS   (REGION + W_WARM)       // region + warmup pad

// ---- Butterworth(4, 0.5) coefficients as compile-time literals ----
#define KD   0.010209481f
#define CB0  (KD)
#define CB1  (4.0f * KD)
#define CB2  (6.0f * KD)
#define CB3  (4.0f * KD)
#define CB4  (KD)
#define CNA1 ( 1.96842778f)     // -a1
#define CNA2 (-1.73586071f)     // -a2
#define CNA3 ( 0.72447081f)     // -a3
#define CNA4 (-0.12038960f)     // -a4

struct Params {
    float4 wq4[W_WARM];            // warmup weights w_j = A^(W-1-j) g (const space)
};

// 16B-granule swizzle: word (chunk c, sample j) -> c*32 + (j ^ ((c&7)<<2)).
// Aligned float4 groups stay contiguous; every 128-bit smem access phase in
// stage/warmup/compute/output is bank-conflict-free.
__device__ __forceinline__ int sidx4(int c, int j) {
    return c * L_CHUNK + (j ^ ((c & 7) << 2));
}

__device__ __forceinline__ void cpa16(unsigned dst_smem, const void* src) {
    asm volatile("cp.async.cg.shared.global [%0], [%1], 16;\n"
                 :: "r"(dst_smem), "l"(src));
}

// One DF2T step, coefficient multiplies in FFMA-imm form.
__device__ __forceinline__ float iir_step(float xv, float& z0, float& z1,
                                          float& z2, float& z3) {
    float yv = fmaf(CB0, xv, z0);
    z0 = fmaf(CB1, xv, z1); z0 = fmaf(CNA1, yv, z0);
    z1 = fmaf(CB2, xv, z2); z1 = fmaf(CNA2, yv, z1);
    z2 = fmaf(CB3, xv, z3); z2 = fmaf(CNA3, yv, z2);
    z3 = CB4 * xv;          z3 = fmaf(CNA4, yv, z3);
    return yv;
}

__device__ __forceinline__ size_t region_base(int r) {
    return (size_t)(r >> 4) * T_LEN + (size_t)(r & (RB_PER_ROW - 1)) * REGION;
}

// Issue async stage of one region (+ its 32-float warmup pad) into smbuf.
__device__ __forceinline__ void stage_region(float* smbuf, const float* __restrict__ x,
                                             int r, int t) {
    const size_t gb = region_base(r);
    const float4* xin = reinterpret_cast<const float4*>(x + gb);
    unsigned smb = (unsigned)__cvta_generic_to_shared(smbuf);
#pragma unroll
    for (int i = 0; i < REGION / (4 * CPB); i++) {   // 8 iters
        int vidx = i * CPB + t;
        int c = vidx >> 3;
        int j = (vidx & 7) * 4;
        cpa16(smb + sidx4(c, j) * 4u, xin + vidx);
    }
    if (t < W_WARM / 4) {                 // pad: x[region_start-32 .. -1]
        if ((r & (RB_PER_ROW - 1)) != 0)
            cpa16(smb + (REGION + 4 * t) * 4u,
                  reinterpret_cast<const float4*>(x + gb - W_WARM) + t);
        else
            reinterpret_cast<float4*>(smbuf + REGION)[t] =
                make_float4(0.f, 0.f, 0.f, 0.f);
    }
    asm volatile("cp.async.commit_group;\n");
}

__global__ void __launch_bounds__(CPB, 6) fused_kernel(const float* __restrict__ x,
                                                       float* __restrict__ y,
                                                       Params P) {
    __shared__ float sm[2][BUFWORDS];

    const int t    = threadIdx.x;
    const int r0   = blockIdx.x * NR;

    stage_region(sm[0], x, r0, t);

#pragma unroll
    for (int it = 0; it < NR; it++) {
        float* smb = sm[it & 1];
        const int r = r0 + it;

        // prefetch next region into the other buffer, then drain current group
        if (it + 1 < NR) {
            stage_region(sm[(it & 1) ^ 1], x, r + 1, t);
            asm volatile("cp.async.wait_group 1;\n");
        } else {
            asm volatile("cp.async.wait_group 0;\n");
        }
        __syncthreads();

        // ---- warmup: state from previous 32 samples (prev chunk or pad) ----
        float z0 = 0.f, z1 = 0.f, z2 = 0.f, z3 = 0.f;
        {
            const int wbase = (t > 0) ? (t - 1) * L_CHUNK : REGION;
            const int wk    = (t > 0) ? ((t - 1) & 7) << 2 : 0;
#pragma unroll
            for (int q = 0; q < W_WARM / 4; q++) {
                float4 xv = *reinterpret_cast<const float4*>(
                    &smb[wbase + ((4 * q) ^ wk)]);
                float4 w0 = P.wq4[4 * q + 0], w1 = P.wq4[4 * q + 1];
                float4 w2 = P.wq4[4 * q + 2], w3 = P.wq4[4 * q + 3];
                z0 = fmaf(w0.x, xv.x, z0); z1 = fmaf(w0.y, xv.x, z1);
                z2 = fmaf(w0.z, xv.x, z2); z3 = fmaf(w0.w, xv.x, z3);
                z0 = fmaf(w1.x, xv.y, z0); z1 = fmaf(w1.y, xv.y, z1);
                z2 = fmaf(w1.z, xv.y, z2); z3 = fmaf(w1.w, xv.y, z3);
                z0 = fmaf(w2.x, xv.z, z0); z1 = fmaf(w2.y, xv.z, z1);
                z2 = fmaf(w2.z, xv.z, z2); z3 = fmaf(w2.w, xv.z, z3);
                z0 = fmaf(w3.x, xv.w, z0); z1 = fmaf(w3.y, xv.w, z1);
                z2 = fmaf(w3.z, xv.w, z2); z3 = fmaf(w3.w, xv.w, z3);
            }
        }
        __syncthreads();   // warmup reads done before in-place overwrite

        // ---- main: DF2T over own chunk, y in place ----
#pragma unroll
        for (int q = 0; q < L_CHUNK / 4; q++) {
            float4* ap = reinterpret_cast<float4*>(&smb[sidx4(t, 4 * q)]);
            float4 xv = *ap;
            float4 ov;
            ov.x = iir_step(xv.x, z0, z1, z2, z3);
            ov.y = iir_step(xv.y, z0, z1, z2, z3);
            ov.z = iir_step(xv.z, z0, z1, z2, z3);
            ov.w = iir_step(xv.w, z0, z1, z2, z3);
            *ap = ov;
        }
        __syncthreads();

        // ---- output: swizzled LDS.128 -> coalesced STG.128 ----
        float4* yout = reinterpret_cast<float4*>(y + region_base(r));
#pragma unroll
        for (int i = 0; i < REGION / (4 * CPB); i++) {
            int vidx = i * CPB + t;
            int c = vidx >> 3;
            int j = (vidx & 7) * 4;
            yout[vidx] = *reinterpret_cast<const float4*>(&smb[sidx4(c, j)]);
        }
        __syncthreads();   // buffer reusable by the prefetch two iterations on
    }
}

// ---------------- host ----------------

extern "C" void kernel_launch(void* const* d_in, const int* in_sizes, int n_in,
                              void* d_out, int out_size) {
    const float* x = (const float*)d_in[0];
    float* y = (float*)d_out;

    // Same coefficients as the device literals, in double for weight generation.
    const double kd = 0.010209481;
    const double bcoef[5] = { kd, 4.0 * kd, 6.0 * kd, 4.0 * kd, kd };
    const double acoef[5] = { 1.0, -1.96842778, 1.73586071,
                              -0.72447081, 0.12038960 };

    // state transition: z' = A z + g x  (DF2T with y eliminated)
    double A[16] = {0};
    for (int i = 0; i < 4; i++) {
        A[i * 4 + 0] -= acoef[i + 1];
        if (i < 3) A[i * 4 + (i + 1)] += 1.0;
    }
    double g[4];
    for (int i = 0; i < 4; i++) g[i] = bcoef[i + 1] - acoef[i + 1] * bcoef[0];

    Params P;
    // warmup weights: w_j = A^(W-1-j) g  (oldest sample gets highest power)
    double wv[4] = { g[0], g[1], g[2], g[3] };
    for (int j = W_WARM - 1; j >= 0; j--) {
        P.wq4[j] = make_float4((float)wv[0], (float)wv[1],
                               (float)wv[2], (float)wv[3]);
        double nv[4];
        for (int i = 0; i < 4; i++) {
            nv[i] = 0.0;
            for (int k2 = 0; k2 < 4; k2++) nv[i] += A[i * 4 + k2] * wv[k2];
        }
        for (int i = 0; i < 4; i++) wv[i] = nv[i];
    }

    fused_kernel<<<GRID, CPB>>>(x, y, P);
}

// round 15
// speedup vs baseline: 1.0894x; 1.0894x over previous
#include <cuda_runtime.h>
#include <math.h>

#define BATCH      256
#define T_LEN      65536
#define L_CHUNK    32
#define W_WARM     32                      // window = exactly previous chunk
#define CPB        128                     // chunks (= threads) per block
#define REGION     (CPB * L_CHUNK)         // 4096 floats = 16KB
#define RB_PER_ROW (T_LEN / REGION)        // 16 blocks per batch row
#define NBLK       (BATCH * RB_PER_ROW)    // 4096 blocks

// ---- Butterworth(4, 0.5) coefficients as compile-time literals ----
// w = 4 tan(pi/8); bilinear transform. sum(b) == sum(a) (DC gain 1).
#define KD   0.010209481f
#define CB0  (KD)
#define CB1  (4.0f * KD)
#define CB2  (6.0f * KD)
#define CB3  (4.0f * KD)
#define CB4  (KD)
#define CNA1 ( 1.96842778f)     // -a1
#define CNA2 (-1.73586071f)     // -a2
#define CNA3 ( 0.72447081f)     // -a3
#define CNA4 (-0.12038960f)     // -a4

struct Params {
    float4 wq4[W_WARM];            // warmup weights w_j = A^(W-1-j) g (const space)
};

// 16B-granule swizzle: word (chunk c, sample j) -> c*32 + (j ^ ((c&7)<<2)).
// XOR touches only bits 2..4 (j<32), aligned float4 groups stay contiguous,
// and every phase of every 128-bit smem op below is bank-conflict-free.
__device__ __forceinline__ int sidx4(int c, int j) {
    return c * L_CHUNK + (j ^ ((c & 7) << 2));
}

__device__ __forceinline__ void cpa16(unsigned dst_smem, const void* src) {
    asm volatile("cp.async.cg.shared.global [%0], [%1], 16;\n"
                 :: "r"(dst_smem), "l"(src));
}

// One DF2T step, coefficient multiplies in FFMA-imm form (rt_SMSP=1).
__device__ __forceinline__ float iir_step(float xv, float& z0, float& z1,
                                          float& z2, float& z3) {
    float yv = fmaf(CB0, xv, z0);
    z0 = fmaf(CB1, xv, z1); z0 = fmaf(CNA1, yv, z0);
    z1 = fmaf(CB2, xv, z2); z1 = fmaf(CNA2, yv, z1);
    z2 = fmaf(CB3, xv, z3); z2 = fmaf(CNA3, yv, z2);
    z3 = CB4 * xv;          z3 = fmaf(CNA4, yv, z3);
    return yv;
}

__global__ void __launch_bounds__(CPB, 13) fused_kernel(const float* __restrict__ x,
                                                        float* __restrict__ y,
                                                        Params P) {
    // main region + 32-float pad region (words REGION..REGION+31) for the
    // block-leading chunk's warmup window; unified addressing (wk = 0 there).
    __shared__ float4 smv[(REGION + W_WARM) / 4];
    float* sm = reinterpret_cast<float*>(smv);

    const int t   = threadIdx.x;
    const int blk = blockIdx.x;
    const int rb  = blk & (RB_PER_ROW - 1);
    const size_t gbase = (size_t)(blk >> 4) * T_LEN + (size_t)rb * REGION;

    // ---- stage: coalesced 16B cp.async -> swizzled smem ----
    const float4* xin = reinterpret_cast<const float4*>(x + gbase);
    unsigned smb = (unsigned)__cvta_generic_to_shared(sm);
#pragma unroll
    for (int i = 0; i < REGION / (4 * CPB); i++) {   // 8 iters
        int vidx = i * CPB + t;
        int c = vidx >> 3;                // 8 float4 per chunk
        int j = (vidx & 7) * 4;
        cpa16(smb + sidx4(c, j) * 4u, xin + vidx);
    }
    if (t < W_WARM / 4) {                 // pad: x[block_start-32 .. -1]
        float4 d = make_float4(0.f, 0.f, 0.f, 0.f);
        if (rb != 0)
            d = reinterpret_cast<const float4*>(x + gbase - W_WARM)[t];
        reinterpret_cast<float4*>(&sm[REGION])[t] = d;
    }
    asm volatile("cp.async.commit_group;\n");
    asm volatile("cp.async.wait_group 0;\n");
    __syncthreads();

    // ---- warmup: state = sum over previous 32 samples, w_j = A^(31-j) g ----
    // Window == previous chunk (t>0) or the pad region (t==0; zeros at row
    // start reproduce the zero-initial-condition state exactly).
    float z0 = 0.f, z1 = 0.f, z2 = 0.f, z3 = 0.f;
    {
        const int wbase = (t > 0) ? (t - 1) * L_CHUNK : REGION;
        const int wk    = (t > 0) ? ((t - 1) & 7) << 2 : 0;
#pragma unroll
        for (int q = 0; q < W_WARM / 4; q++) {
            float4 xv = *reinterpret_cast<const float4*>(&sm[wbase + ((4 * q) ^ wk)]);
            float4 w0 = P.wq4[4 * q + 0], w1 = P.wq4[4 * q + 1];
            float4 w2 = P.wq4[4 * q + 2], w3 = P.wq4[4 * q + 3];
            z0 = fmaf(w0.x, xv.x, z0); z1 = fmaf(w0.y, xv.x, z1);
            z2 = fmaf(w0.z, xv.x, z2); z3 = fmaf(w0.w, xv.x, z3);
            z0 = fmaf(w1.x, xv.y, z0); z1 = fmaf(w1.y, xv.y, z1);
            z2 = fmaf(w1.z, xv.y, z2); z3 = fmaf(w1.w, xv.y, z3);
            z0 = fmaf(w2.x, xv.z, z0); z1 = fmaf(w2.y, xv.z, z1);
            z2 = fmaf(w2.z, xv.z, z2); z3 = fmaf(w2.w, xv.z, z3);
            z0 = fmaf(w3.x, xv.w, z0); z1 = fmaf(w3.y, xv.w, z1);
            z2 = fmaf(w3.z, xv.w, z2); z3 = fmaf(w3.w, xv.w, z3);
        }
    }
    __syncthreads();   // all warmup reads done before in-place overwrite

    // ---- main: DF2T over own chunk (vectorized smem IO), y in place ----
#pragma unroll
    for (int q = 0; q < L_CHUNK / 4; q++) {
        float4* ap = reinterpret_cast<float4*>(&sm[sidx4(t, 4 * q)]);
        float4 xv = *ap;
        float4 ov;
        ov.x = iir_step(xv.x, z0, z1, z2, z3);
        ov.y = iir_step(xv.y, z0, z1, z2, z3);
        ov.z = iir_step(xv.z, z0, z1, z2, z3);
        ov.w = iir_step(xv.w, z0, z1, z2, z3);
        *ap = ov;
    }
    __syncthreads();

    // ---- output: swizzled LDS.128 -> coalesced STG.128 ----
    float4* yout = reinterpret_cast<float4*>(y + gbase);
#pragma unroll
    for (int i = 0; i < REGION / (4 * CPB); i++) {
        int vidx = i * CPB + t;
        int c = vidx >> 3;
        int j = (vidx & 7) * 4;
        yout[vidx] = *reinterpret_cast<const float4*>(&sm[sidx4(c, j)]);
    }
}

// ---------------- host ----------------

extern "C" void kernel_launch(void* const* d_in, const int* in_sizes, int n_in,
                              void* d_out, int out_size) {
    const float* x = (const float*)d_in[0];
    float* y = (float*)d_out;

    // Same coefficients as the device literals, in double for weight generation.
    const double kd = 0.010209481;
    const double bcoef[5] = { kd, 4.0 * kd, 6.0 * kd, 4.0 * kd, kd };
    const double acoef[5] = { 1.0, -1.96842778, 1.73586071,
                              -0.72447081, 0.12038960 };

    // state transition: z' = A z + g x  (DF2T with y eliminated)
    double A[16] = {0};
    for (int i = 0; i < 4; i++) {
        A[i * 4 + 0] -= acoef[i + 1];
        if (i < 3) A[i * 4 + (i + 1)] += 1.0;
    }
    double g[4];
    for (int i = 0; i < 4; i++) g[i] = bcoef[i + 1] - acoef[i + 1] * bcoef[0];

    Params P;
    // warmup weights: w_j = A^(W-1-j) g  (oldest sample gets highest power)
    double wv[4] = { g[0], g[1], g[2], g[3] };
    for (int j = W_WARM - 1; j >= 0; j--) {
        P.wq4[j] = make_float4((float)wv[0], (float)wv[1],
                               (float)wv[2], (float)wv[3]);
        double nv[4];
        for (int i = 0; i < 4; i++) {
            nv[i] = 0.0;
            for (int k2 = 0; k2 < 4; k2++) nv[i] += A[i * 4 + k2] * wv[k2];
        }
        for (int i = 0; i < 4; i++) wv[i] = nv[i];
    }

    fused_kernel<<<NBLK, CPB>>>(x, y, P);
}